// round 13
// baseline (speedup 1.0000x reference)
#include <cuda_runtime.h>
#include <cuda_fp16.h>
#include <math.h>
#include <cstdint>

// ---------------- problem constants ----------------
constexpr int BB    = 8;
constexpr int NTOK  = 4096;   // 64x64
constexpr int CD    = 512;
constexpr int NHEAD = 8;
constexpr int HDIM  = 64;
constexpr int MT    = 64;     // 8x8 reduced tokens
constexpr int KIM   = 64 * CD;        // 32768
constexpr int SPLITK = 16;

// gemm engine
constexpr int BK = 32;
constexpr int PA = 40;
constexpr int PB = 136;
constexpr int STAGES = 4;
constexpr int ASZ = 128 * PA;
constexpr int BSZ = BK * PB;
constexpr int SMEM_BYTES = STAGES * (ASZ + BSZ) * 2;   // 75776

// attention smem: Qs 128*72 + Ks 64*72 + Vs 64*72 halves
constexpr int PQ = 72;
constexpr int ATT_SMEM = (128 * PQ + 2 * 64 * PQ) * 2;  // 36864

// ---------------- device scratch ----------------
__device__ __half g_qh[(size_t)BB * NHEAD * NTOK * HDIM]; // [b,nh,n,hd] fp16 *0.125
__device__ __half g_xc[(size_t)BB * NTOK * CD];
__device__ __half g_cwr[(size_t)KIM * CD];
__device__ __half g_wqr[CD * CD];
__device__ __half g_wpr[CD * CD];
__device__ __half g_wkvr[CD * 2 * CD];
__device__ float  g_part[(size_t)SPLITK * BB * MT * CD];
__device__ __half g_lnh[BB * MT * CD];
__device__ __half g_kvh[2 * BB * NHEAD * MT * HDIM];      // [f][b][nh][m][d]
__device__ __half g_attn[(size_t)BB * NTOK * CD];

__device__ __forceinline__ uint32_t smem_u32(const void* p) {
    uint32_t a;
    asm("{ .reg .u64 t; cvta.to.shared.u64 t, %1; cvt.u32.u64 %0, t; }" : "=r"(a) : "l"(p));
    return a;
}
#define CP16(dst, src) \
    asm volatile("cp.async.cg.shared.global [%0], [%1], 16;" :: "r"(dst), "l"(src))
#define CP_COMMIT() asm volatile("cp.async.commit_group;" ::: "memory")
#define CP_WAIT2()  asm volatile("cp.async.wait_group 2;" ::: "memory")

#define LDSM_X4(r0, r1, r2, r3, a) \
    asm volatile("ldmatrix.sync.aligned.m8n8.x4.shared.b16 {%0,%1,%2,%3}, [%4];" \
        : "=r"(r0), "=r"(r1), "=r"(r2), "=r"(r3) : "r"(a))
#define LDSM_X4T(r0, r1, r2, r3, a) \
    asm volatile("ldmatrix.sync.aligned.m8n8.x4.trans.shared.b16 {%0,%1,%2,%3}, [%4];" \
        : "=r"(r0), "=r"(r1), "=r"(r2), "=r"(r3) : "r"(a))

__device__ __forceinline__ void mma16(float c[4], uint32_t a0, uint32_t a1,
                                      uint32_t a2, uint32_t a3,
                                      uint32_t b0, uint32_t b1) {
    asm volatile(
        "mma.sync.aligned.m16n8k16.row.col.f32.f16.f16.f32 "
        "{%0,%1,%2,%3}, {%4,%5,%6,%7}, {%8,%9}, {%0,%1,%2,%3};"
        : "+f"(c[0]), "+f"(c[1]), "+f"(c[2]), "+f"(c[3])
        : "r"(a0), "r"(a1), "r"(a2), "r"(a3), "r"(b0), "r"(b1));
}
__device__ __forceinline__ float ex2f(float x) {
    float r; asm("ex2.approx.ftz.f32 %0, %1;" : "=f"(r) : "f"(x)); return r;
}
__device__ __forceinline__ uint32_t h2u(__half2 h) {
    uint32_t u; asm("mov.b32 %0, %1;" : "=r"(u) : "r"(*(uint32_t*)&h)); return u;
}

// ---------------- GEMM body ----------------
// AMODE 0: A row-major.  AMODE 1: conv im2col gather.
// SMODE 0: fp32 +bias.  SMODE 1: split-K partial.  SMODE 2: q permute.  SMODE 3: kv head-split.
template <int AMODE, int SMODE>
__device__ __forceinline__ void gemm_body(
    const __half* __restrict__ A, const __half* __restrict__ B,
    float* __restrict__ C, int M, int N, int K, int kPerZ,
    const float* __restrict__ bias, int bx, int by, int bz, __half* sm)
{
    __half* As = sm;
    __half* Bs = sm + STAGES * ASZ;
    const uint32_t smA = smem_u32(As);
    const uint32_t smB = smem_u32(Bs);

    const int tid = threadIdx.x;
    const int wid = tid >> 5, lid = tid & 31;
    const int gid = lid >> 2, t4 = lid & 3;
    const int wm = wid >> 1, wn = wid & 1;
    const int n0 = bx * 128, m0 = by * 128;
    const int k0 = bz * kPerZ;
    const int nIter = kPerZ / BK;

    float acc[4][8][4];
#pragma unroll
    for (int i = 0; i < 4; i++)
#pragma unroll
        for (int j = 0; j < 8; j++)
#pragma unroll
            for (int r = 0; r < 4; r++) acc[i][j][r] = 0.f;

    auto load_tile = [&](int it) {
        const int stage = it & (STAGES - 1);
        const int kt = k0 + it * BK;
        const uint32_t ab = smA + stage * (ASZ * 2);
        const uint32_t bb = smB + stage * (BSZ * 2);
#pragma unroll
        for (int j = 0; j < 4; j++) {
            int cid = tid + j * 128;
            int r = cid >> 2, kc = (cid & 3) * 8;
            const __half* src;
            if (AMODE == 0) {
                src = A + (size_t)(m0 + r) * K + kt + kc;
            } else {
                int pg = m0 + r;
                int b = pg >> 6, p = pg & 63;
                int kk = kt + kc;
                int rs = kk >> 9, ci = kk & 511;
                int n = ((p >> 3) * 8 + (rs >> 3)) * 64 + (p & 7) * 8 + (rs & 7);
                src = A + (((size_t)((b << 12) + n)) << 9) + ci;
            }
            CP16(ab + (uint32_t)(r * PA + kc) * 2, src);
        }
#pragma unroll
        for (int j = 0; j < 4; j++) {
            int cid = tid + j * 128;
            int k = cid >> 4, nc = (cid & 15) * 8;
            CP16(bb + (uint32_t)(k * PB + nc) * 2,
                 B + (size_t)(kt + k) * N + n0 + nc);
        }
        CP_COMMIT();
    };

#pragma unroll
    for (int it = 0; it < STAGES - 1; it++) {
        if (it < nIter) load_tile(it); else CP_COMMIT();
    }

    const int aRow = (lid & 15);
    const int aCol = 8 * (lid >> 4);
    const int bRow = (lid & 7) + 8 * ((lid >> 3) & 1);
    const int bCol = 8 * (lid >> 4);

    for (int it = 0; it < nIter; it++) {
        CP_WAIT2();
        __syncthreads();
        if (it + STAGES - 1 < nIter) load_tile(it + STAGES - 1);
        else CP_COMMIT();

        const int stage = it & (STAGES - 1);
        const uint32_t Ab = smA + stage * (ASZ * 2);
        const uint32_t Bb = smB + stage * (BSZ * 2);
#pragma unroll
        for (int ks = 0; ks < 2; ks++) {
            const int kb = ks * 16;
            uint32_t af[4][4], bf[8][2];
#pragma unroll
            for (int fm = 0; fm < 4; fm++) {
                const int m = wm * 64 + fm * 16 + aRow;
                LDSM_X4(af[fm][0], af[fm][1], af[fm][2], af[fm][3],
                        Ab + (uint32_t)(m * PA + kb + aCol) * 2);
            }
#pragma unroll
            for (int g = 0; g < 4; g++) {
                const int nn = wn * 64 + g * 16 + bCol;
                LDSM_X4T(bf[2 * g][0], bf[2 * g][1], bf[2 * g + 1][0], bf[2 * g + 1][1],
                         Bb + (uint32_t)((kb + bRow) * PB + nn) * 2);
            }
#pragma unroll
            for (int fm = 0; fm < 4; fm++)
#pragma unroll
                for (int fn = 0; fn < 8; fn++)
                    mma16(acc[fm][fn], af[fm][0], af[fm][1], af[fm][2], af[fm][3],
                          bf[fn][0], bf[fn][1]);
        }
    }

    if (SMODE == 2) {
        __syncthreads();
        __half* tile = sm;          // [128][136]
#pragma unroll
        for (int fm = 0; fm < 4; fm++)
#pragma unroll
            for (int fn = 0; fn < 8; fn++) {
                const int lc = wn * 64 + fn * 8 + t4 * 2;
#pragma unroll
                for (int h = 0; h < 2; h++) {
                    const int lr = wm * 64 + fm * 16 + gid + h * 8;
                    *(__half2*)&tile[lr * 136 + lc] =
                        __floats2half2_rn(acc[fm][fn][2 * h + 0] * 0.125f,
                                          acc[fm][fn][2 * h + 1] * 0.125f);
                }
            }
        __syncthreads();
        const int b = m0 >> 12;
        const int hd0 = n0 >> 3;
#pragma unroll
        for (int i = tid; i < 2048; i += 128) {
            const int nh = i >> 8;
            const int row = (i & 255) >> 1, ch = i & 1;
            __half tmp[8];
#pragma unroll
            for (int j = 0; j < 8; j++)
                tmp[j] = tile[row * 136 + (ch * 8 + j) * 8 + nh];
            const int n = (m0 & 4095) + row;
            *(uint4*)(g_qh + (((size_t)(b * NHEAD + nh) * NTOK + n)) * HDIM
                      + hd0 + ch * 8) = *(uint4*)tmp;
        }
        return;
    }

#pragma unroll
    for (int fm = 0; fm < 4; fm++) {
#pragma unroll
        for (int fn = 0; fn < 8; fn++) {
            const int col = n0 + wn * 64 + fn * 8 + t4 * 2;
#pragma unroll
            for (int h = 0; h < 2; h++) {
                const int row = m0 + wm * 64 + fm * 16 + gid + h * 8;
                float v0 = acc[fm][fn][2 * h + 0];
                float v1 = acc[fm][fn][2 * h + 1];
                if (SMODE == 0) {
                    if (bias) { v0 += bias[col]; v1 += bias[col + 1]; }
                    *(float2*)(C + (size_t)row * N + col) = make_float2(v0, v1);
                } else if (SMODE == 1) {
                    *(float2*)(C + (size_t)bz * M * N + (size_t)row * N + col) =
                        make_float2(v0, v1);
                } else {
                    const int f = col >> 9, nh = (col >> 6) & 7, d = col & 63;
                    const int b = row >> 6, m = row & 63;
                    *(__half2*)(g_kvh + ((((size_t)f * BB + b) * NHEAD + nh) * MT + m)
                                * HDIM + d) = __floats2half2_rn(v0, v1);
                }
            }
        }
    }
}

// ---------------- attention body (dynamic smem) ----------------
__device__ __forceinline__ void attn_body(int bh, int bxx, __half* sm)
{
    const int b = bh >> 3, nh = bh & 7;
    const int qb = bxx * 128;
    const int tid = threadIdx.x;
    const int wid = tid >> 5, lid = tid & 31;
    const int gid = lid >> 2, t4 = lid & 3;

    __half (*Qs)[PQ] = (__half(*)[PQ])sm;
    __half (*Ks)[PQ] = (__half(*)[PQ])(sm + 128 * PQ);
    __half (*Vs)[PQ] = (__half(*)[PQ])(sm + 128 * PQ + 64 * PQ);

    for (int i = tid; i < 128 * 8; i += 128) {
        int row = i >> 3, c8 = (i & 7) * 8;
        *(uint4*)&Qs[row][c8] =
            *(const uint4*)(g_qh + ((size_t)bh * NTOK + qb + row) * HDIM + c8);
    }
    const __half* kbase = g_kvh + ((size_t)(b * NHEAD + nh)) * MT * HDIM;
    const __half* vbase = kbase + (size_t)BB * NHEAD * MT * HDIM;
    for (int i = tid; i < 64 * 8; i += 128) {
        int m = i >> 3, c8 = (i & 7) * 8;
        *(uint4*)&Ks[m][c8] = *(const uint4*)(kbase + m * HDIM + c8);
        *(uint4*)&Vs[m][c8] = *(const uint4*)(vbase + m * HDIM + c8);
    }
    __syncthreads();

    const int aRow = (lid & 15);
    const int aCol = 8 * (lid >> 4);
    const int bRow = (lid & 7) + 8 * ((lid >> 3) & 1);
    const int bCol = 8 * (lid >> 4);
    const uint32_t Qb = smem_u32(&Qs[0][0]);
    const uint32_t Kb = smem_u32(&Ks[0][0]);
    const uint32_t Vb = smem_u32(&Vs[0][0]);

    float S[2][8][4];
#pragma unroll
    for (int i = 0; i < 2; i++)
#pragma unroll
        for (int j = 0; j < 8; j++)
#pragma unroll
            for (int r = 0; r < 4; r++) S[i][j][r] = 0.f;

#pragma unroll
    for (int kc = 0; kc < 4; kc++) {
        uint32_t af[2][4], bf[8][2];
#pragma unroll
        for (int fm = 0; fm < 2; fm++) {
            const int m = wid * 32 + fm * 16 + aRow;
            LDSM_X4(af[fm][0], af[fm][1], af[fm][2], af[fm][3],
                    Qb + (uint32_t)(m * PQ + kc * 16 + aCol) * 2);
        }
#pragma unroll
        for (int g = 0; g < 4; g++) {
            const int nn = g * 16 + aRow;
            uint32_t r0, r1, r2, r3;
            LDSM_X4(r0, r1, r2, r3, Kb + (uint32_t)(nn * PQ + kc * 16 + aCol) * 2);
            bf[2 * g][0] = r0; bf[2 * g][1] = r2;
            bf[2 * g + 1][0] = r1; bf[2 * g + 1][1] = r3;
        }
#pragma unroll
        for (int fm = 0; fm < 2; fm++)
#pragma unroll
            for (int fn = 0; fn < 8; fn++)
                mma16(S[fm][fn], af[fm][0], af[fm][1], af[fm][2], af[fm][3],
                      bf[fn][0], bf[fn][1]);
    }

    constexpr float L2E = 1.4426950408889634f;
    float rsum[2][2] = {{0.f, 0.f}, {0.f, 0.f}};
#pragma unroll
    for (int fm = 0; fm < 2; fm++)
#pragma unroll
        for (int fn = 0; fn < 8; fn++) {
            float w0 = ex2f(S[fm][fn][0] * L2E);
            float w1 = ex2f(S[fm][fn][1] * L2E);
            float w2 = ex2f(S[fm][fn][2] * L2E);
            float w3 = ex2f(S[fm][fn][3] * L2E);
            S[fm][fn][0] = w0; S[fm][fn][1] = w1;
            S[fm][fn][2] = w2; S[fm][fn][3] = w3;
            rsum[fm][0] += w0 + w1;
            rsum[fm][1] += w2 + w3;
        }
#pragma unroll
    for (int fm = 0; fm < 2; fm++)
#pragma unroll
        for (int h = 0; h < 2; h++) {
            rsum[fm][h] += __shfl_xor_sync(0xffffffffu, rsum[fm][h], 1);
            rsum[fm][h] += __shfl_xor_sync(0xffffffffu, rsum[fm][h], 2);
        }

    uint32_t pf[2][4][4];
#pragma unroll
    for (int fm = 0; fm < 2; fm++)
#pragma unroll
        for (int kc = 0; kc < 4; kc++) {
            pf[fm][kc][0] = h2u(__floats2half2_rn(S[fm][2 * kc][0],     S[fm][2 * kc][1]));
            pf[fm][kc][1] = h2u(__floats2half2_rn(S[fm][2 * kc][2],     S[fm][2 * kc][3]));
            pf[fm][kc][2] = h2u(__floats2half2_rn(S[fm][2 * kc + 1][0], S[fm][2 * kc + 1][1]));
            pf[fm][kc][3] = h2u(__floats2half2_rn(S[fm][2 * kc + 1][2], S[fm][2 * kc + 1][3]));
        }

    float O[2][8][4];
#pragma unroll
    for (int i = 0; i < 2; i++)
#pragma unroll
        for (int j = 0; j < 8; j++)
#pragma unroll
            for (int r = 0; r < 4; r++) O[i][j][r] = 0.f;

#pragma unroll
    for (int kc = 0; kc < 4; kc++) {
        uint32_t bf[8][2];
#pragma unroll
        for (int g = 0; g < 4; g++) {
            LDSM_X4T(bf[2 * g][0], bf[2 * g][1], bf[2 * g + 1][0], bf[2 * g + 1][1],
                     Vb + (uint32_t)((kc * 16 + bRow) * PQ + g * 16 + bCol) * 2);
        }
#pragma unroll
        for (int fm = 0; fm < 2; fm++)
#pragma unroll
            for (int fn = 0; fn < 8; fn++)
                mma16(O[fm][fn], pf[fm][kc][0], pf[fm][kc][1], pf[fm][kc][2], pf[fm][kc][3],
                      bf[fn][0], bf[fn][1]);
    }

#pragma unroll
    for (int fm = 0; fm < 2; fm++) {
        const float inv0 = 1.f / rsum[fm][0];
        const float inv1 = 1.f / rsum[fm][1];
#pragma unroll
        for (int fn = 0; fn < 8; fn++) {
            const int d = fn * 8 + t4 * 2;
            const int r0 = qb + wid * 32 + fm * 16 + gid;
            __half* dst0 = g_attn + ((size_t)(b * NTOK + r0)) * CD + nh * HDIM + d;
            *(__half2*)dst0 = __floats2half2_rn(O[fm][fn][0] * inv0, O[fm][fn][1] * inv0);
            __half* dst1 = g_attn + ((size_t)(b * NTOK + r0 + 8)) * CD + nh * HDIM + d;
            *(__half2*)dst1 = __floats2half2_rn(O[fm][fn][2] * inv1, O[fm][fn][3] * inv1);
        }
    }
}

// ---------------- kernels ----------------
template <int AMODE, int SMODE>
__global__ __launch_bounds__(128, 2)
void mma_gemm(const __half* __restrict__ A, const __half* __restrict__ B,
              float* __restrict__ C, int M, int N, int K, int kPerZ,
              const float* __restrict__ bias)
{
    extern __shared__ __half sm[];
    gemm_body<AMODE, SMODE>(A, B, C, M, N, K, kPerZ, bias,
                            blockIdx.x, blockIdx.y, blockIdx.z, sm);
}

// merged conv split-K + q GEMM
__global__ __launch_bounds__(128, 2)
void fused_qconv_k(const __half* __restrict__ xc, const __half* __restrict__ cwr,
                   const __half* __restrict__ wqr, float* __restrict__ part)
{
    extern __shared__ __half sm[];
    const int bid = blockIdx.x;
    if (bid < 256) {
        const int z = bid >> 4, rem = bid & 15;
        gemm_body<1, 1>(xc, cwr, part, BB * MT, CD, KIM, KIM / SPLITK, nullptr,
                        rem & 3, rem >> 2, z, sm);
    } else {
        const int i = bid - 256;
        gemm_body<0, 2>(xc, wqr, nullptr, BB * NTOK, CD, CD, CD, nullptr,
                        i & 3, i >> 2, 0, sm);
    }
}

// standalone attention chunk (512 blocks: 32 qb x 16 bh)
__global__ __launch_bounds__(128)
void attn_k(int bh0)
{
    extern __shared__ __half sm[];
    attn_body(bh0 + (int)blockIdx.y, blockIdx.x, sm);
}

// fused tail: blocks [0,256) = Wp GEMM on prev chunk; [256,768) = attn on cur chunk
__global__ __launch_bounds__(128, 2)
void fused_attn_wp_k(const __half* __restrict__ wpSrc, float* __restrict__ wpDst,
                     const __half* __restrict__ wpr, const float* __restrict__ bp,
                     int bh0)
{
    extern __shared__ __half sm[];
    const int bid = blockIdx.x;
    if (bid < 256) {
        gemm_body<0, 0>(wpSrc, wpr, wpDst, 2 * NTOK, CD, CD, CD, bp,
                        bid & 3, bid >> 2, 0, sm);
    } else {
        const int i = bid - 256;
        attn_body(bh0 + (i >> 5), i & 31, sm);
    }
}

// ---------------- conversions ----------------
__global__ void round_h_k(const float* __restrict__ src, __half* __restrict__ dst, int n8)
{
    int i = blockIdx.x * 256 + threadIdx.x;
    if (i >= n8) return;
    float4 v0 = *(const float4*)(src + 8 * (size_t)i);
    float4 v1 = *(const float4*)(src + 8 * (size_t)i + 4);
    __half2* d = (__half2*)(dst + 8 * (size_t)i);
    d[0] = __floats2half2_rn(v0.x, v0.y);
    d[1] = __floats2half2_rn(v0.z, v0.w);
    d[2] = __floats2half2_rn(v1.x, v1.y);
    d[3] = __floats2half2_rn(v1.z, v1.w);
}

__global__ void round_w3_k(const float* __restrict__ Wq, const float* __restrict__ Wkv,
                           const float* __restrict__ Wp)
{
    int i = blockIdx.x * 256 + threadIdx.x;
    const float* src;
    __half* dst;
    int off;
    if (i < 32768)        { src = Wq;  dst = g_wqr;  off = i; }
    else if (i < 98304)   { src = Wkv; dst = g_wkvr; off = i - 32768; }
    else                  { src = Wp;  dst = g_wpr;  off = i - 98304; }
    float4 v0 = *(const float4*)(src + 8 * (size_t)off);
    float4 v1 = *(const float4*)(src + 8 * (size_t)off + 4);
    __half2* d = (__half2*)(dst + 8 * (size_t)off);
    d[0] = __floats2half2_rn(v0.x, v0.y);
    d[1] = __floats2half2_rn(v0.z, v0.w);
    d[2] = __floats2half2_rn(v1.x, v1.y);
    d[3] = __floats2half2_rn(v1.z, v1.w);
}

// ---------------- fused split-K reduce + layernorm -> fp16 ----------------
__global__ void reduce_ln_k(const float* __restrict__ gamma, const float* __restrict__ beta)
{
    int row = blockIdx.x;
    int t = threadIdx.x;
    const float* p = g_part + (size_t)row * CD;
    float a = 0.f, b2 = 0.f;
#pragma unroll
    for (int z = 0; z < SPLITK; z++) {
        a  += p[(size_t)z * (BB * MT * CD) + t];
        b2 += p[(size_t)z * (BB * MT * CD) + t + 256];
    }
    float s = a + b2, s2 = a * a + b2 * b2;
#pragma unroll
    for (int o = 16; o; o >>= 1) {
        s  += __shfl_down_sync(0xffffffffu, s,  o);
        s2 += __shfl_down_sync(0xffffffffu, s2, o);
    }
    __shared__ float rs[8], rs2[8];
    int w = t >> 5, l = t & 31;
    if (l == 0) { rs[w] = s; rs2[w] = s2; }
    __syncthreads();
    if (t == 0) {
        float S = 0.f, S2 = 0.f;
        for (int q2 = 0; q2 < 8; q2++) { S += rs[q2]; S2 += rs2[q2]; }
        float mu = S / (float)CD;
        float var = S2 / (float)CD - mu * mu;
        rs[0] = mu;
        rs2[0] = rsqrtf(var + 1e-3f);
    }
    __syncthreads();
    float mu = rs[0], inv = rs2[0];
    __half* out = g_lnh + (size_t)row * CD;
    out[t]       = __float2half((a  - mu) * inv * gamma[t]       + beta[t]);
    out[t + 256] = __float2half((b2 - mu) * inv * gamma[t + 256] + beta[t + 256]);
}

// ---------------- launch ----------------
extern "C" void kernel_launch(void* const* d_in, const int* in_sizes, int n_in,
                              void* d_out, int out_size)
{
    const float* x     = (const float*)d_in[0];
    const float* Wq    = (const float*)d_in[1];
    const float* Wkv   = (const float*)d_in[2];
    const float* convw = (const float*)d_in[3];
    const float* gamma = (const float*)d_in[4];
    const float* beta  = (const float*)d_in[5];
    const float* Wp    = (const float*)d_in[6];
    const float* bp    = (const float*)d_in[7];
    float* out = (float*)d_out;

    __half *xc, *cwr, *wqr, *wpr, *wkvr, *lnh, *attnp;
    float *part;
    cudaGetSymbolAddress((void**)&xc,    g_xc);
    cudaGetSymbolAddress((void**)&cwr,   g_cwr);
    cudaGetSymbolAddress((void**)&wqr,   g_wqr);
    cudaGetSymbolAddress((void**)&wpr,   g_wpr);
    cudaGetSymbolAddress((void**)&wkvr,  g_wkvr);
    cudaGetSymbolAddress((void**)&part,  g_part);
    cudaGetSymbolAddress((void**)&lnh,   g_lnh);
    cudaGetSymbolAddress((void**)&attnp, g_attn);

    static cudaStream_t sB = nullptr;
    static cudaEvent_t eFork = nullptr, eCW = nullptr;
    if (!sB) {
        cudaStreamCreateWithFlags(&sB, cudaStreamNonBlocking);
        cudaEventCreateWithFlags(&eFork, cudaEventDisableTiming);
        cudaEventCreateWithFlags(&eCW,   cudaEventDisableTiming);
        cudaFuncSetAttribute(mma_gemm<0, 0>, cudaFuncAttributeMaxDynamicSharedMemorySize, SMEM_BYTES);
        cudaFuncSetAttribute(mma_gemm<0, 3>, cudaFuncAttributeMaxDynamicSharedMemorySize, SMEM_BYTES);
        cudaFuncSetAttribute(fused_qconv_k, cudaFuncAttributeMaxDynamicSharedMemorySize, SMEM_BYTES);
        cudaFuncSetAttribute(fused_attn_wp_k, cudaFuncAttributeMaxDynamicSharedMemorySize, SMEM_BYTES);
    }

    // fork: stream B converts conv_w
    cudaEventRecord(eFork, 0);
    cudaStreamWaitEvent(sB, eFork, 0);
    {
        int n8c = KIM * CD / 8;
        round_h_k<<<(n8c + 255) / 256, 256, 0, sB>>>(convw, cwr, n8c);
        cudaEventRecord(eCW, sB);
    }

    // main: x + small weights
    {
        int n8x = BB * NTOK * CD / 8;
        round_h_k<<<(n8x + 255) / 256, 256>>>(x, xc, n8x);
        round_w3_k<<<512, 256>>>(Wq, Wkv, Wp);
    }
    cudaStreamWaitEvent(0, eCW, 0);

    // merged conv-splitK + q GEMM (1280 CTAs)
    fused_qconv_k<<<1280, 128, SMEM_BYTES>>>(xc, cwr, wqr, part);

    // reduce+LN, kv GEMM -> g_kvh
    reduce_ln_k<<<BB * MT, 256>>>(gamma, beta);
    mma_gemm<0, 3><<<dim3((2 * CD) / 128, (BB * MT) / 128), 128, SMEM_BYTES>>>(
        lnh, wkvr, nullptr, BB * MT, 2 * CD, CD, CD, nullptr);

    // tail: 4 chunks of 2 batches, fused attn(c) || Wp(c-1), single stream
    constexpr int ROWS = 2 * NTOK;              // 8192 rows / chunk
    attn_k<<<dim3(32, 16), 128, ATT_SMEM>>>(0);
    for (int c = 1; c < 4; c++) {
        fused_attn_wp_k<<<768, 128, SMEM_BYTES>>>(
            attnp + (size_t)(c - 1) * ROWS * CD, out + (size_t)(c - 1) * ROWS * CD,
            wpr, bp, c * 16);
    }
    mma_gemm<0, 0><<<dim3(CD / 128, ROWS / 128), 128, SMEM_BYTES>>>(
        attnp + (size_t)3 * ROWS * CD, wpr, out + (size_t)3 * ROWS * CD,
        ROWS, CD, CD, CD, bp);
}

// round 14
// speedup vs baseline: 1.0001x; 1.0001x over previous
#include <cuda_runtime.h>
#include <cuda_fp16.h>
#include <math.h>
#include <cstdint>

// ---------------- problem constants ----------------
constexpr int BB    = 8;
constexpr int NTOK  = 4096;   // 64x64
constexpr int CD    = 512;
constexpr int NHEAD = 8;
constexpr int HDIM  = 64;
constexpr int MT    = 64;     // 8x8 reduced tokens
constexpr int KIM   = 64 * CD;        // 32768
constexpr int SPLITK = 16;

// gemm engine
constexpr int BK = 32;
constexpr int PA = 40;
constexpr int PB = 136;
constexpr int STAGES = 4;
constexpr int ASZ = 128 * PA;
constexpr int BSZ = BK * PB;
constexpr int SMEM_BYTES = STAGES * (ASZ + BSZ) * 2;   // 75776

// attention smem: Qs 128*72 + Ks 64*72 + Vs 64*72 halves
constexpr int PQ = 72;
constexpr int ATT_SMEM = (128 * PQ + 2 * 64 * PQ) * 2;  // 36864

// ---------------- device scratch ----------------
__device__ __half g_qh[(size_t)BB * NHEAD * NTOK * HDIM]; // [b,nh,n,hd] fp16 *0.125
__device__ __half g_xc[(size_t)BB * NTOK * CD];
__device__ __half g_cwr[(size_t)KIM * CD];
__device__ __half g_wqr[CD * CD];
__device__ __half g_wpr[CD * CD];
__device__ __half g_wkvr[CD * 2 * CD];
__device__ float  g_part[(size_t)SPLITK * BB * MT * CD];
__device__ __half g_lnh[BB * MT * CD];
__device__ __half g_kvh[2 * BB * NHEAD * MT * HDIM];      // [f][b][nh][m][d]
__device__ __half g_attn[(size_t)BB * NTOK * CD];

__device__ __forceinline__ uint32_t smem_u32(const void* p) {
    uint32_t a;
    asm("{ .reg .u64 t; cvta.to.shared.u64 t, %1; cvt.u32.u64 %0, t; }" : "=r"(a) : "l"(p));
    return a;
}
#define CP16(dst, src) \
    asm volatile("cp.async.cg.shared.global [%0], [%1], 16;" :: "r"(dst), "l"(src))
#define CP_COMMIT() asm volatile("cp.async.commit_group;" ::: "memory")
#define CP_WAIT2()  asm volatile("cp.async.wait_group 2;" ::: "memory")

#define LDSM_X4(r0, r1, r2, r3, a) \
    asm volatile("ldmatrix.sync.aligned.m8n8.x4.shared.b16 {%0,%1,%2,%3}, [%4];" \
        : "=r"(r0), "=r"(r1), "=r"(r2), "=r"(r3) : "r"(a))
#define LDSM_X4T(r0, r1, r2, r3, a) \
    asm volatile("ldmatrix.sync.aligned.m8n8.x4.trans.shared.b16 {%0,%1,%2,%3}, [%4];" \
        : "=r"(r0), "=r"(r1), "=r"(r2), "=r"(r3) : "r"(a))

__device__ __forceinline__ void mma16(float c[4], uint32_t a0, uint32_t a1,
                                      uint32_t a2, uint32_t a3,
                                      uint32_t b0, uint32_t b1) {
    asm volatile(
        "mma.sync.aligned.m16n8k16.row.col.f32.f16.f16.f32 "
        "{%0,%1,%2,%3}, {%4,%5,%6,%7}, {%8,%9}, {%0,%1,%2,%3};"
        : "+f"(c[0]), "+f"(c[1]), "+f"(c[2]), "+f"(c[3])
        : "r"(a0), "r"(a1), "r"(a2), "r"(a3), "r"(b0), "r"(b1));
}
__device__ __forceinline__ float ex2f(float x) {
    float r; asm("ex2.approx.ftz.f32 %0, %1;" : "=f"(r) : "f"(x)); return r;
}
__device__ __forceinline__ uint32_t h2u(__half2 h) {
    uint32_t u; asm("mov.b32 %0, %1;" : "=r"(u) : "r"(*(uint32_t*)&h)); return u;
}

// ---------------- GEMM body ----------------
// AMODE 0: A row-major.  AMODE 1: conv im2col gather.
// SMODE 0: fp32 +bias.  SMODE 1: split-K partial.  SMODE 2: q permute.  SMODE 3: kv head-split.
template <int AMODE, int SMODE>
__device__ __forceinline__ void gemm_body(
    const __half* __restrict__ A, const __half* __restrict__ B,
    float* __restrict__ C, int M, int N, int K, int kPerZ,
    const float* __restrict__ bias, int bx, int by, int bz, __half* sm)
{
    __half* As = sm;
    __half* Bs = sm + STAGES * ASZ;
    const uint32_t smA = smem_u32(As);
    const uint32_t smB = smem_u32(Bs);

    const int tid = threadIdx.x;
    const int wid = tid >> 5, lid = tid & 31;
    const int gid = lid >> 2, t4 = lid & 3;
    const int wm = wid >> 1, wn = wid & 1;
    const int n0 = bx * 128, m0 = by * 128;
    const int k0 = bz * kPerZ;
    const int nIter = kPerZ / BK;

    float acc[4][8][4];
#pragma unroll
    for (int i = 0; i < 4; i++)
#pragma unroll
        for (int j = 0; j < 8; j++)
#pragma unroll
            for (int r = 0; r < 4; r++) acc[i][j][r] = 0.f;

    auto load_tile = [&](int it) {
        const int stage = it & (STAGES - 1);
        const int kt = k0 + it * BK;
        const uint32_t ab = smA + stage * (ASZ * 2);
        const uint32_t bb = smB + stage * (BSZ * 2);
#pragma unroll
        for (int j = 0; j < 4; j++) {
            int cid = tid + j * 128;
            int r = cid >> 2, kc = (cid & 3) * 8;
            const __half* src;
            if (AMODE == 0) {
                src = A + (size_t)(m0 + r) * K + kt + kc;
            } else {
                int pg = m0 + r;
                int b = pg >> 6, p = pg & 63;
                int kk = kt + kc;
                int rs = kk >> 9, ci = kk & 511;
                int n = ((p >> 3) * 8 + (rs >> 3)) * 64 + (p & 7) * 8 + (rs & 7);
                src = A + (((size_t)((b << 12) + n)) << 9) + ci;
            }
            CP16(ab + (uint32_t)(r * PA + kc) * 2, src);
        }
#pragma unroll
        for (int j = 0; j < 4; j++) {
            int cid = tid + j * 128;
            int k = cid >> 4, nc = (cid & 15) * 8;
            CP16(bb + (uint32_t)(k * PB + nc) * 2,
                 B + (size_t)(kt + k) * N + n0 + nc);
        }
        CP_COMMIT();
    };

#pragma unroll
    for (int it = 0; it < STAGES - 1; it++) {
        if (it < nIter) load_tile(it); else CP_COMMIT();
    }

    const int aRow = (lid & 15);
    const int aCol = 8 * (lid >> 4);
    const int bRow = (lid & 7) + 8 * ((lid >> 3) & 1);
    const int bCol = 8 * (lid >> 4);

    for (int it = 0; it < nIter; it++) {
        CP_WAIT2();
        __syncthreads();
        if (it + STAGES - 1 < nIter) load_tile(it + STAGES - 1);
        else CP_COMMIT();

        const int stage = it & (STAGES - 1);
        const uint32_t Ab = smA + stage * (ASZ * 2);
        const uint32_t Bb = smB + stage * (BSZ * 2);
#pragma unroll
        for (int ks = 0; ks < 2; ks++) {
            const int kb = ks * 16;
            uint32_t af[4][4], bf[8][2];
#pragma unroll
            for (int fm = 0; fm < 4; fm++) {
                const int m = wm * 64 + fm * 16 + aRow;
                LDSM_X4(af[fm][0], af[fm][1], af[fm][2], af[fm][3],
                        Ab + (uint32_t)(m * PA + kb + aCol) * 2);
            }
#pragma unroll
            for (int g = 0; g < 4; g++) {
                const int nn = wn * 64 + g * 16 + bCol;
                LDSM_X4T(bf[2 * g][0], bf[2 * g][1], bf[2 * g + 1][0], bf[2 * g + 1][1],
                         Bb + (uint32_t)((kb + bRow) * PB + nn) * 2);
            }
#pragma unroll
            for (int fm = 0; fm < 4; fm++)
#pragma unroll
                for (int fn = 0; fn < 8; fn++)
                    mma16(acc[fm][fn], af[fm][0], af[fm][1], af[fm][2], af[fm][3],
                          bf[fn][0], bf[fn][1]);
        }
    }

    if (SMODE == 2) {
        __syncthreads();
        __half* tile = sm;          // [128][136]
#pragma unroll
        for (int fm = 0; fm < 4; fm++)
#pragma unroll
            for (int fn = 0; fn < 8; fn++) {
                const int lc = wn * 64 + fn * 8 + t4 * 2;
#pragma unroll
                for (int h = 0; h < 2; h++) {
                    const int lr = wm * 64 + fm * 16 + gid + h * 8;
                    *(__half2*)&tile[lr * 136 + lc] =
                        __floats2half2_rn(acc[fm][fn][2 * h + 0] * 0.125f,
                                          acc[fm][fn][2 * h + 1] * 0.125f);
                }
            }
        __syncthreads();
        const int b = m0 >> 12;
        const int hd0 = n0 >> 3;
#pragma unroll
        for (int i = tid; i < 2048; i += 128) {
            const int nh = i >> 8;
            const int row = (i & 255) >> 1, ch = i & 1;
            __half tmp[8];
#pragma unroll
            for (int j = 0; j < 8; j++)
                tmp[j] = tile[row * 136 + (ch * 8 + j) * 8 + nh];
            const int n = (m0 & 4095) + row;
            *(uint4*)(g_qh + (((size_t)(b * NHEAD + nh) * NTOK + n)) * HDIM
                      + hd0 + ch * 8) = *(uint4*)tmp;
        }
        return;
    }

#pragma unroll
    for (int fm = 0; fm < 4; fm++) {
#pragma unroll
        for (int fn = 0; fn < 8; fn++) {
            const int col = n0 + wn * 64 + fn * 8 + t4 * 2;
#pragma unroll
            for (int h = 0; h < 2; h++) {
                const int row = m0 + wm * 64 + fm * 16 + gid + h * 8;
                float v0 = acc[fm][fn][2 * h + 0];
                float v1 = acc[fm][fn][2 * h + 1];
                if (SMODE == 0) {
                    if (bias) { v0 += bias[col]; v1 += bias[col + 1]; }
                    *(float2*)(C + (size_t)row * N + col) = make_float2(v0, v1);
                } else if (SMODE == 1) {
                    *(float2*)(C + (size_t)bz * M * N + (size_t)row * N + col) =
                        make_float2(v0, v1);
                } else {
                    const int f = col >> 9, nh = (col >> 6) & 7, d = col & 63;
                    const int b = row >> 6, m = row & 63;
                    *(__half2*)(g_kvh + ((((size_t)f * BB + b) * NHEAD + nh) * MT + m)
                                * HDIM + d) = __floats2half2_rn(v0, v1);
                }
            }
        }
    }
}

// ---------------- attention body (dynamic smem) ----------------
__device__ __forceinline__ void attn_body(int bh, int bxx, __half* sm)
{
    const int b = bh >> 3, nh = bh & 7;
    const int qb = bxx * 128;
    const int tid = threadIdx.x;
    const int wid = tid >> 5, lid = tid & 31;
    const int gid = lid >> 2, t4 = lid & 3;

    __half (*Qs)[PQ] = (__half(*)[PQ])sm;
    __half (*Ks)[PQ] = (__half(*)[PQ])(sm + 128 * PQ);
    __half (*Vs)[PQ] = (__half(*)[PQ])(sm + 128 * PQ + 64 * PQ);

    for (int i = tid; i < 128 * 8; i += 128) {
        int row = i >> 3, c8 = (i & 7) * 8;
        *(uint4*)&Qs[row][c8] =
            *(const uint4*)(g_qh + ((size_t)bh * NTOK + qb + row) * HDIM + c8);
    }
    const __half* kbase = g_kvh + ((size_t)(b * NHEAD + nh)) * MT * HDIM;
    const __half* vbase = kbase + (size_t)BB * NHEAD * MT * HDIM;
    for (int i = tid; i < 64 * 8; i += 128) {
        int m = i >> 3, c8 = (i & 7) * 8;
        *(uint4*)&Ks[m][c8] = *(const uint4*)(kbase + m * HDIM + c8);
        *(uint4*)&Vs[m][c8] = *(const uint4*)(vbase + m * HDIM + c8);
    }
    __syncthreads();

    const int aRow = (lid & 15);
    const int aCol = 8 * (lid >> 4);
    const int bRow = (lid & 7) + 8 * ((lid >> 3) & 1);
    const int bCol = 8 * (lid >> 4);
    const uint32_t Qb = smem_u32(&Qs[0][0]);
    const uint32_t Kb = smem_u32(&Ks[0][0]);
    const uint32_t Vb = smem_u32(&Vs[0][0]);

    float S[2][8][4];
#pragma unroll
    for (int i = 0; i < 2; i++)
#pragma unroll
        for (int j = 0; j < 8; j++)
#pragma unroll
            for (int r = 0; r < 4; r++) S[i][j][r] = 0.f;

#pragma unroll
    for (int kc = 0; kc < 4; kc++) {
        uint32_t af[2][4], bf[8][2];
#pragma unroll
        for (int fm = 0; fm < 2; fm++) {
            const int m = wid * 32 + fm * 16 + aRow;
            LDSM_X4(af[fm][0], af[fm][1], af[fm][2], af[fm][3],
                    Qb + (uint32_t)(m * PQ + kc * 16 + aCol) * 2);
        }
#pragma unroll
        for (int g = 0; g < 4; g++) {
            const int nn = g * 16 + aRow;
            uint32_t r0, r1, r2, r3;
            LDSM_X4(r0, r1, r2, r3, Kb + (uint32_t)(nn * PQ + kc * 16 + aCol) * 2);
            bf[2 * g][0] = r0; bf[2 * g][1] = r2;
            bf[2 * g + 1][0] = r1; bf[2 * g + 1][1] = r3;
        }
#pragma unroll
        for (int fm = 0; fm < 2; fm++)
#pragma unroll
            for (int fn = 0; fn < 8; fn++)
                mma16(S[fm][fn], af[fm][0], af[fm][1], af[fm][2], af[fm][3],
                      bf[fn][0], bf[fn][1]);
    }

    constexpr float L2E = 1.4426950408889634f;
    float rsum[2][2] = {{0.f, 0.f}, {0.f, 0.f}};
#pragma unroll
    for (int fm = 0; fm < 2; fm++)
#pragma unroll
        for (int fn = 0; fn < 8; fn++) {
            float w0 = ex2f(S[fm][fn][0] * L2E);
            float w1 = ex2f(S[fm][fn][1] * L2E);
            float w2 = ex2f(S[fm][fn][2] * L2E);
            float w3 = ex2f(S[fm][fn][3] * L2E);
            S[fm][fn][0] = w0; S[fm][fn][1] = w1;
            S[fm][fn][2] = w2; S[fm][fn][3] = w3;
            rsum[fm][0] += w0 + w1;
            rsum[fm][1] += w2 + w3;
        }
#pragma unroll
    for (int fm = 0; fm < 2; fm++)
#pragma unroll
        for (int h = 0; h < 2; h++) {
            rsum[fm][h] += __shfl_xor_sync(0xffffffffu, rsum[fm][h], 1);
            rsum[fm][h] += __shfl_xor_sync(0xffffffffu, rsum[fm][h], 2);
        }

    uint32_t pf[2][4][4];
#pragma unroll
    for (int fm = 0; fm < 2; fm++)
#pragma unroll
        for (int kc = 0; kc < 4; kc++) {
            pf[fm][kc][0] = h2u(__floats2half2_rn(S[fm][2 * kc][0],     S[fm][2 * kc][1]));
            pf[fm][kc][1] = h2u(__floats2half2_rn(S[fm][2 * kc][2],     S[fm][2 * kc][3]));
            pf[fm][kc][2] = h2u(__floats2half2_rn(S[fm][2 * kc + 1][0], S[fm][2 * kc + 1][1]));
            pf[fm][kc][3] = h2u(__floats2half2_rn(S[fm][2 * kc + 1][2], S[fm][2 * kc + 1][3]));
        }

    float O[2][8][4];
#pragma unroll
    for (int i = 0; i < 2; i++)
#pragma unroll
        for (int j = 0; j < 8; j++)
#pragma unroll
            for (int r = 0; r < 4; r++) O[i][j][r] = 0.f;

#pragma unroll
    for (int kc = 0; kc < 4; kc++) {
        uint32_t bf[8][2];
#pragma unroll
        for (int g = 0; g < 4; g++) {
            LDSM_X4T(bf[2 * g][0], bf[2 * g][1], bf[2 * g + 1][0], bf[2 * g + 1][1],
                     Vb + (uint32_t)((kc * 16 + bRow) * PQ + g * 16 + bCol) * 2);
        }
#pragma unroll
        for (int fm = 0; fm < 2; fm++)
#pragma unroll
            for (int fn = 0; fn < 8; fn++)
                mma16(O[fm][fn], pf[fm][kc][0], pf[fm][kc][1], pf[fm][kc][2], pf[fm][kc][3],
                      bf[fn][0], bf[fn][1]);
    }

#pragma unroll
    for (int fm = 0; fm < 2; fm++) {
        const float inv0 = 1.f / rsum[fm][0];
        const float inv1 = 1.f / rsum[fm][1];
#pragma unroll
        for (int fn = 0; fn < 8; fn++) {
            const int d = fn * 8 + t4 * 2;
            const int r0 = qb + wid * 32 + fm * 16 + gid;
            __half* dst0 = g_attn + ((size_t)(b * NTOK + r0)) * CD + nh * HDIM + d;
            *(__half2*)dst0 = __floats2half2_rn(O[fm][fn][0] * inv0, O[fm][fn][1] * inv0);
            __half* dst1 = g_attn + ((size_t)(b * NTOK + r0 + 8)) * CD + nh * HDIM + d;
            *(__half2*)dst1 = __floats2half2_rn(O[fm][fn][2] * inv1, O[fm][fn][3] * inv1);
        }
    }
}

// ---------------- kernels ----------------
template <int AMODE, int SMODE>
__global__ __launch_bounds__(128, 2)
void mma_gemm(const __half* __restrict__ A, const __half* __restrict__ B,
              float* __restrict__ C, int M, int N, int K, int kPerZ,
              const float* __restrict__ bias)
{
    extern __shared__ __half sm[];
    gemm_body<AMODE, SMODE>(A, B, C, M, N, K, kPerZ, bias,
                            blockIdx.x, blockIdx.y, blockIdx.z, sm);
}

// merged conv split-K + q GEMM
__global__ __launch_bounds__(128, 2)
void fused_qconv_k(const __half* __restrict__ xc, const __half* __restrict__ cwr,
                   const __half* __restrict__ wqr, float* __restrict__ part)
{
    extern __shared__ __half sm[];
    const int bid = blockIdx.x;
    if (bid < 256) {
        const int z = bid >> 4, rem = bid & 15;
        gemm_body<1, 1>(xc, cwr, part, BB * MT, CD, KIM, KIM / SPLITK, nullptr,
                        rem & 3, rem >> 2, z, sm);
    } else {
        const int i = bid - 256;
        gemm_body<0, 2>(xc, wqr, nullptr, BB * NTOK, CD, CD, CD, nullptr,
                        i & 3, i >> 2, 0, sm);
    }
}

// standalone attention chunk (512 blocks: 32 qb x 16 bh)
__global__ __launch_bounds__(128)
void attn_k(int bh0)
{
    extern __shared__ __half sm[];
    attn_body(bh0 + (int)blockIdx.y, blockIdx.x, sm);
}

// fused tail: blocks [0,256) = Wp GEMM on prev chunk; [256,768) = attn on cur chunk
__global__ __launch_bounds__(128, 2)
void fused_attn_wp_k(const __half* __restrict__ wpSrc, float* __restrict__ wpDst,
                     const __half* __restrict__ wpr, const float* __restrict__ bp,
                     int bh0)
{
    extern __shared__ __half sm[];
    const int bid = blockIdx.x;
    if (bid < 256) {
        gemm_body<0, 0>(wpSrc, wpr, wpDst, 2 * NTOK, CD, CD, CD, bp,
                        bid & 3, bid >> 2, 0, sm);
    } else {
        const int i = bid - 256;
        attn_body(bh0 + (i >> 5), i & 31, sm);
    }
}

// ---------------- conversions ----------------
__global__ void round_h_k(const float* __restrict__ src, __half* __restrict__ dst, int n8)
{
    int i = blockIdx.x * 256 + threadIdx.x;
    if (i >= n8) return;
    float4 v0 = *(const float4*)(src + 8 * (size_t)i);
    float4 v1 = *(const float4*)(src + 8 * (size_t)i + 4);
    __half2* d = (__half2*)(dst + 8 * (size_t)i);
    d[0] = __floats2half2_rn(v0.x, v0.y);
    d[1] = __floats2half2_rn(v0.z, v0.w);
    d[2] = __floats2half2_rn(v1.x, v1.y);
    d[3] = __floats2half2_rn(v1.z, v1.w);
}

__global__ void round_w3_k(const float* __restrict__ Wq, const float* __restrict__ Wkv,
                           const float* __restrict__ Wp)
{
    int i = blockIdx.x * 256 + threadIdx.x;
    const float* src;
    __half* dst;
    int off;
    if (i < 32768)        { src = Wq;  dst = g_wqr;  off = i; }
    else if (i < 98304)   { src = Wkv; dst = g_wkvr; off = i - 32768; }
    else                  { src = Wp;  dst = g_wpr;  off = i - 98304; }
    float4 v0 = *(const float4*)(src + 8 * (size_t)off);
    float4 v1 = *(const float4*)(src + 8 * (size_t)off + 4);
    __half2* d = (__half2*)(dst + 8 * (size_t)off);
    d[0] = __floats2half2_rn(v0.x, v0.y);
    d[1] = __floats2half2_rn(v0.z, v0.w);
    d[2] = __floats2half2_rn(v1.x, v1.y);
    d[3] = __floats2half2_rn(v1.z, v1.w);
}

// ---------------- fused split-K reduce + layernorm -> fp16 ----------------
__global__ void reduce_ln_k(const float* __restrict__ gamma, const float* __restrict__ beta)
{
    int row = blockIdx.x;
    int t = threadIdx.x;
    const float* p = g_part + (size_t)row * CD;
    float a = 0.f, b2 = 0.f;
#pragma unroll
    for (int z = 0; z < SPLITK; z++) {
        a  += p[(size_t)z * (BB * MT * CD) + t];
        b2 += p[(size_t)z * (BB * MT * CD) + t + 256];
    }
    float s = a + b2, s2 = a * a + b2 * b2;
#pragma unroll
    for (int o = 16; o; o >>= 1) {
        s  += __shfl_down_sync(0xffffffffu, s,  o);
        s2 += __shfl_down_sync(0xffffffffu, s2, o);
    }
    __shared__ float rs[8], rs2[8];
    int w = t >> 5, l = t & 31;
    if (l == 0) { rs[w] = s; rs2[w] = s2; }
    __syncthreads();
    if (t == 0) {
        float S = 0.f, S2 = 0.f;
        for (int q2 = 0; q2 < 8; q2++) { S += rs[q2]; S2 += rs2[q2]; }
        float mu = S / (float)CD;
        float var = S2 / (float)CD - mu * mu;
        rs[0] = mu;
        rs2[0] = rsqrtf(var + 1e-3f);
    }
    __syncthreads();
    float mu = rs[0], inv = rs2[0];
    __half* out = g_lnh + (size_t)row * CD;
    out[t]       = __float2half((a  - mu) * inv * gamma[t]       + beta[t]);
    out[t + 256] = __float2half((b2 - mu) * inv * gamma[t + 256] + beta[t + 256]);
}

// ---------------- launch ----------------
extern "C" void kernel_launch(void* const* d_in, const int* in_sizes, int n_in,
                              void* d_out, int out_size)
{
    const float* x     = (const float*)d_in[0];
    const float* Wq    = (const float*)d_in[1];
    const float* Wkv   = (const float*)d_in[2];
    const float* convw = (const float*)d_in[3];
    const float* gamma = (const float*)d_in[4];
    const float* beta  = (const float*)d_in[5];
    const float* Wp    = (const float*)d_in[6];
    const float* bp    = (const float*)d_in[7];
    float* out = (float*)d_out;

    __half *xc, *cwr, *wqr, *wpr, *wkvr, *lnh, *attnp;
    float *part;
    cudaGetSymbolAddress((void**)&xc,    g_xc);
    cudaGetSymbolAddress((void**)&cwr,   g_cwr);
    cudaGetSymbolAddress((void**)&wqr,   g_wqr);
    cudaGetSymbolAddress((void**)&wpr,   g_wpr);
    cudaGetSymbolAddress((void**)&wkvr,  g_wkvr);
    cudaGetSymbolAddress((void**)&part,  g_part);
    cudaGetSymbolAddress((void**)&lnh,   g_lnh);
    cudaGetSymbolAddress((void**)&attnp, g_attn);

    static cudaStream_t sB = nullptr;
    static cudaEvent_t eFork = nullptr, eCW = nullptr;
    if (!sB) {
        cudaStreamCreateWithFlags(&sB, cudaStreamNonBlocking);
        cudaEventCreateWithFlags(&eFork, cudaEventDisableTiming);
        cudaEventCreateWithFlags(&eCW,   cudaEventDisableTiming);
        cudaFuncSetAttribute(mma_gemm<0, 0>, cudaFuncAttributeMaxDynamicSharedMemorySize, SMEM_BYTES);
        cudaFuncSetAttribute(mma_gemm<0, 3>, cudaFuncAttributeMaxDynamicSharedMemorySize, SMEM_BYTES);
        cudaFuncSetAttribute(fused_qconv_k, cudaFuncAttributeMaxDynamicSharedMemorySize, SMEM_BYTES);
        cudaFuncSetAttribute(fused_attn_wp_k, cudaFuncAttributeMaxDynamicSharedMemorySize, SMEM_BYTES);
    }

    // fork: stream B converts conv_w
    cudaEventRecord(eFork, 0);
    cudaStreamWaitEvent(sB, eFork, 0);
    {
        int n8c = KIM * CD / 8;
        round_h_k<<<(n8c + 255) / 256, 256, 0, sB>>>(convw, cwr, n8c);
        cudaEventRecord(eCW, sB);
    }

    // main: x + small weights
    {
        int n8x = BB * NTOK * CD / 8;
        round_h_k<<<(n8x + 255) / 256, 256>>>(x, xc, n8x);
        round_w3_k<<<512, 256>>>(Wq, Wkv, Wp);
    }
    cudaStreamWaitEvent(0, eCW, 0);

    // merged conv-splitK + q GEMM (1280 CTAs)
    fused_qconv_k<<<1280, 128, SMEM_BYTES>>>(xc, cwr, wqr, part);

    // reduce+LN, kv GEMM -> g_kvh
    reduce_ln_k<<<BB * MT, 256>>>(gamma, beta);
    mma_gemm<0, 3><<<dim3((2 * CD) / 128, (BB * MT) / 128), 128, SMEM_BYTES>>>(
        lnh, wkvr, nullptr, BB * MT, 2 * CD, CD, CD, nullptr);

    // tail: 4 chunks of 2 batches, fused attn(c) || Wp(c-1), single stream
    constexpr int ROWS = 2 * NTOK;              // 8192 rows / chunk
    attn_k<<<dim3(32, 16), 128, ATT_SMEM>>>(0);
    for (int c = 1; c < 4; c++) {
        fused_attn_wp_k<<<768, 128, SMEM_BYTES>>>(
            attnp + (size_t)(c - 1) * ROWS * CD, out + (size_t)(c - 1) * ROWS * CD,
            wpr, bp, c * 16);
    }
    mma_gemm<0, 0><<<dim3(CD / 128, ROWS / 128), 128, SMEM_BYTES>>>(
        attnp + (size_t)3 * ROWS * CD, wpr, out + (size_t)3 * ROWS * CD,
        ROWS, CD, CD, CD, bp);
}

// round 15
// speedup vs baseline: 1.0932x; 1.0930x over previous
#include <cuda_runtime.h>
#include <cuda_fp16.h>
#include <math.h>
#include <cstdint>

// ---------------- problem constants ----------------
constexpr int BB    = 8;
constexpr int NTOK  = 4096;   // 64x64
constexpr int CD    = 512;
constexpr int NHEAD = 8;
constexpr int HDIM  = 64;
constexpr int MT    = 64;     // 8x8 reduced tokens
constexpr int KIM   = 64 * CD;        // 32768
constexpr int SPLITK = 16;

// gemm engine
constexpr int BK = 32;
constexpr int PA = 40;
constexpr int PB = 136;
constexpr int STAGES = 4;
constexpr int ASZ = 128 * PA;
constexpr int BSZ = BK * PB;
constexpr int SMEM_BYTES = STAGES * (ASZ + BSZ) * 2;   // 75776

// attention smem
constexpr int PQ = 72;
constexpr int ATT_SMEM = (128 * PQ + 2 * 64 * PQ) * 2;  // 36864

// ---------------- device scratch ----------------
__device__ __half g_qh[(size_t)BB * NHEAD * NTOK * HDIM]; // [b,nh,n,hd] fp16 *0.125
__device__ __half g_xc[(size_t)BB * NTOK * CD];
__device__ __half g_cwr[(size_t)KIM * CD];
__device__ __half g_wqr[CD * CD];
__device__ __half g_wpr[CD * CD];
__device__ __half g_wkvr[CD * 2 * CD];
__device__ float  g_part[(size_t)SPLITK * BB * MT * CD];
__device__ __half g_lnh[BB * MT * CD];
__device__ __half g_kvh[2 * BB * NHEAD * MT * HDIM];      // [f][b][nh][m][d]
__device__ __half g_attn[(size_t)BB * NTOK * CD];

__device__ __forceinline__ uint32_t smem_u32(const void* p) {
    uint32_t a;
    asm("{ .reg .u64 t; cvta.to.shared.u64 t, %1; cvt.u32.u64 %0, t; }" : "=r"(a) : "l"(p));
    return a;
}
#define CP16(dst, src) \
    asm volatile("cp.async.cg.shared.global [%0], [%1], 16;" :: "r"(dst), "l"(src))
#define CP_COMMIT() asm volatile("cp.async.commit_group;" ::: "memory")
#define CP_WAIT2()  asm volatile("cp.async.wait_group 2;" ::: "memory")

#define LDSM_X4(r0, r1, r2, r3, a) \
    asm volatile("ldmatrix.sync.aligned.m8n8.x4.shared.b16 {%0,%1,%2,%3}, [%4];" \
        : "=r"(r0), "=r"(r1), "=r"(r2), "=r"(r3) : "r"(a))
#define LDSM_X4T(r0, r1, r2, r3, a) \
    asm volatile("ldmatrix.sync.aligned.m8n8.x4.trans.shared.b16 {%0,%1,%2,%3}, [%4];" \
        : "=r"(r0), "=r"(r1), "=r"(r2), "=r"(r3) : "r"(a))

__device__ __forceinline__ void mma16(float c[4], uint32_t a0, uint32_t a1,
                                      uint32_t a2, uint32_t a3,
                                      uint32_t b0, uint32_t b1) {
    asm volatile(
        "mma.sync.aligned.m16n8k16.row.col.f32.f16.f16.f32 "
        "{%0,%1,%2,%3}, {%4,%5,%6,%7}, {%8,%9}, {%0,%1,%2,%3};"
        : "+f"(c[0]), "+f"(c[1]), "+f"(c[2]), "+f"(c[3])
        : "r"(a0), "r"(a1), "r"(a2), "r"(a3), "r"(b0), "r"(b1));
}
__device__ __forceinline__ float ex2f(float x) {
    float r; asm("ex2.approx.ftz.f32 %0, %1;" : "=f"(r) : "f"(x)); return r;
}
__device__ __forceinline__ uint32_t h2u(__half2 h) {
    uint32_t u; asm("mov.b32 %0, %1;" : "=r"(u) : "r"(*(uint32_t*)&h)); return u;
}

// ---------------- GEMM body ----------------
// AMODE 0: A row-major.  AMODE 1: conv im2col gather.
// SMODE 0: fp32 +bias.  SMODE 1: split-K partial.  SMODE 2: q permute.  SMODE 3: kv head-split.
template <int AMODE, int SMODE>
__device__ __forceinline__ void gemm_body(
    const __half* __restrict__ A, const __half* __restrict__ B,
    float* __restrict__ C, int M, int N, int K, int kPerZ,
    const float* __restrict__ bias, int bx, int by, int bz, __half* sm)
{
    __half* As = sm;
    __half* Bs = sm + STAGES * ASZ;
    const uint32_t smA = smem_u32(As);
    const uint32_t smB = smem_u32(Bs);

    const int tid = threadIdx.x;
    const int wid = tid >> 5, lid = tid & 31;
    const int gid = lid >> 2, t4 = lid & 3;
    const int wm = wid >> 1, wn = wid & 1;
    const int n0 = bx * 128, m0 = by * 128;
    const int k0 = bz * kPerZ;
    const int nIter = kPerZ / BK;

    float acc[4][8][4];
#pragma unroll
    for (int i = 0; i < 4; i++)
#pragma unroll
        for (int j = 0; j < 8; j++)
#pragma unroll
            for (int r = 0; r < 4; r++) acc[i][j][r] = 0.f;

    auto load_tile = [&](int it) {
        const int stage = it & (STAGES - 1);
        const int kt = k0 + it * BK;
        const uint32_t ab = smA + stage * (ASZ * 2);
        const uint32_t bb = smB + stage * (BSZ * 2);
#pragma unroll
        for (int j = 0; j < 4; j++) {
            int cid = tid + j * 128;
            int r = cid >> 2, kc = (cid & 3) * 8;
            const __half* src;
            if (AMODE == 0) {
                src = A + (size_t)(m0 + r) * K + kt + kc;
            } else {
                int pg = m0 + r;
                int b = pg >> 6, p = pg & 63;
                int kk = kt + kc;
                int rs = kk >> 9, ci = kk & 511;
                int n = ((p >> 3) * 8 + (rs >> 3)) * 64 + (p & 7) * 8 + (rs & 7);
                src = A + (((size_t)((b << 12) + n)) << 9) + ci;
            }
            CP16(ab + (uint32_t)(r * PA + kc) * 2, src);
        }
#pragma unroll
        for (int j = 0; j < 4; j++) {
            int cid = tid + j * 128;
            int k = cid >> 4, nc = (cid & 15) * 8;
            CP16(bb + (uint32_t)(k * PB + nc) * 2,
                 B + (size_t)(kt + k) * N + n0 + nc);
        }
        CP_COMMIT();
    };

#pragma unroll
    for (int it = 0; it < STAGES - 1; it++) {
        if (it < nIter) load_tile(it); else CP_COMMIT();
    }

    const int aRow = (lid & 15);
    const int aCol = 8 * (lid >> 4);
    const int bRow = (lid & 7) + 8 * ((lid >> 3) & 1);
    const int bCol = 8 * (lid >> 4);

    for (int it = 0; it < nIter; it++) {
        CP_WAIT2();
        __syncthreads();
        if (it + STAGES - 1 < nIter) load_tile(it + STAGES - 1);
        else CP_COMMIT();

        const int stage = it & (STAGES - 1);
        const uint32_t Ab = smA + stage * (ASZ * 2);
        const uint32_t Bb = smB + stage * (BSZ * 2);
#pragma unroll
        for (int ks = 0; ks < 2; ks++) {
            const int kb = ks * 16;
            uint32_t af[4][4], bf[8][2];
#pragma unroll
            for (int fm = 0; fm < 4; fm++) {
                const int m = wm * 64 + fm * 16 + aRow;
                LDSM_X4(af[fm][0], af[fm][1], af[fm][2], af[fm][3],
                        Ab + (uint32_t)(m * PA + kb + aCol) * 2);
            }
#pragma unroll
            for (int g = 0; g < 4; g++) {
                const int nn = wn * 64 + g * 16 + bCol;
                LDSM_X4T(bf[2 * g][0], bf[2 * g][1], bf[2 * g + 1][0], bf[2 * g + 1][1],
                         Bb + (uint32_t)((kb + bRow) * PB + nn) * 2);
            }
#pragma unroll
            for (int fm = 0; fm < 4; fm++)
#pragma unroll
                for (int fn = 0; fn < 8; fn++)
                    mma16(acc[fm][fn], af[fm][0], af[fm][1], af[fm][2], af[fm][3],
                          bf[fn][0], bf[fn][1]);
        }
    }

    if (SMODE == 2) {
        __syncthreads();
        __half* tile = sm;          // [128][136]
#pragma unroll
        for (int fm = 0; fm < 4; fm++)
#pragma unroll
            for (int fn = 0; fn < 8; fn++) {
                const int lc = wn * 64 + fn * 8 + t4 * 2;
#pragma unroll
                for (int h = 0; h < 2; h++) {
                    const int lr = wm * 64 + fm * 16 + gid + h * 8;
                    *(__half2*)&tile[lr * 136 + lc] =
                        __floats2half2_rn(acc[fm][fn][2 * h + 0] * 0.125f,
                                          acc[fm][fn][2 * h + 1] * 0.125f);
                }
            }
        __syncthreads();
        const int b = m0 >> 12;
        const int hd0 = n0 >> 3;
#pragma unroll
        for (int i = tid; i < 2048; i += 128) {
            const int nh = i >> 8;
            const int row = (i & 255) >> 1, ch = i & 1;
            __half tmp[8];
#pragma unroll
            for (int j = 0; j < 8; j++)
                tmp[j] = tile[row * 136 + (ch * 8 + j) * 8 + nh];
            const int n = (m0 & 4095) + row;
            *(uint4*)(g_qh + (((size_t)(b * NHEAD + nh) * NTOK + n)) * HDIM
                      + hd0 + ch * 8) = *(uint4*)tmp;
        }
        return;
    }

#pragma unroll
    for (int fm = 0; fm < 4; fm++) {
#pragma unroll
        for (int fn = 0; fn < 8; fn++) {
            const int col = n0 + wn * 64 + fn * 8 + t4 * 2;
#pragma unroll
            for (int h = 0; h < 2; h++) {
                const int row = m0 + wm * 64 + fm * 16 + gid + h * 8;
                float v0 = acc[fm][fn][2 * h + 0];
                float v1 = acc[fm][fn][2 * h + 1];
                if (SMODE == 0) {
                    if (bias) { v0 += bias[col]; v1 += bias[col + 1]; }
                    *(float2*)(C + (size_t)row * N + col) = make_float2(v0, v1);
                } else if (SMODE == 1) {
                    *(float2*)(C + (size_t)bz * M * N + (size_t)row * N + col) =
                        make_float2(v0, v1);
                } else {
                    const int f = col >> 9, nh = (col >> 6) & 7, d = col & 63;
                    const int b = row >> 6, m = row & 63;
                    *(__half2*)(g_kvh + ((((size_t)f * BB + b) * NHEAD + nh) * MT + m)
                                * HDIM + d) = __floats2half2_rn(v0, v1);
                }
            }
        }
    }
}

// ---------------- kernels ----------------
template <int AMODE, int SMODE>
__global__ __launch_bounds__(128, 2)
void mma_gemm(const __half* __restrict__ A, const __half* __restrict__ B,
              float* __restrict__ C, int M, int N, int K, int kPerZ,
              const float* __restrict__ bias)
{
    extern __shared__ __half sm[];
    gemm_body<AMODE, SMODE>(A, B, C, M, N, K, kPerZ, bias,
                            blockIdx.x, blockIdx.y, blockIdx.z, sm);
}

// merged conv split-K + q GEMM
__global__ __launch_bounds__(128, 2)
void fused_qconv_k(const __half* __restrict__ xc, const __half* __restrict__ cwr,
                   const __half* __restrict__ wqr, float* __restrict__ part)
{
    extern __shared__ __half sm[];
    const int bid = blockIdx.x;
    if (bid < 256) {
        const int z = bid >> 4, rem = bid & 15;
        gemm_body<1, 1>(xc, cwr, part, BB * MT, CD, KIM, KIM / SPLITK, nullptr,
                        rem & 3, rem >> 2, z, sm);
    } else {
        const int i = bid - 256;
        gemm_body<0, 2>(xc, wqr, nullptr, BB * NTOK, CD, CD, CD, nullptr,
                        i & 3, i >> 2, 0, sm);
    }
}

// ---------------- attention ----------------
__global__ __launch_bounds__(128)
void attn_k()
{
    extern __shared__ __half smd[];
    const int bh = blockIdx.y;
    const int b = bh >> 3, nh = bh & 7;
    const int qb = blockIdx.x * 128;
    const int tid = threadIdx.x;
    const int wid = tid >> 5, lid = tid & 31;
    const int gid = lid >> 2, t4 = lid & 3;

    __half (*Qs)[PQ] = (__half(*)[PQ])smd;
    __half (*Ks)[PQ] = (__half(*)[PQ])(smd + 128 * PQ);
    __half (*Vs)[PQ] = (__half(*)[PQ])(smd + 128 * PQ + 64 * PQ);

    for (int i = tid; i < 128 * 8; i += 128) {
        int row = i >> 3, c8 = (i & 7) * 8;
        *(uint4*)&Qs[row][c8] =
            *(const uint4*)(g_qh + ((size_t)bh * NTOK + qb + row) * HDIM + c8);
    }
    const __half* kbase = g_kvh + ((size_t)(b * NHEAD + nh)) * MT * HDIM;
    const __half* vbase = kbase + (size_t)BB * NHEAD * MT * HDIM;
    for (int i = tid; i < 64 * 8; i += 128) {
        int m = i >> 3, c8 = (i & 7) * 8;
        *(uint4*)&Ks[m][c8] = *(const uint4*)(kbase + m * HDIM + c8);
        *(uint4*)&Vs[m][c8] = *(const uint4*)(vbase + m * HDIM + c8);
    }
    __syncthreads();

    const int aRow = (lid & 15);
    const int aCol = 8 * (lid >> 4);
    const int bRow = (lid & 7) + 8 * ((lid >> 3) & 1);
    const int bCol = 8 * (lid >> 4);
    const uint32_t Qb = smem_u32(&Qs[0][0]);
    const uint32_t Kb = smem_u32(&Ks[0][0]);
    const uint32_t Vb = smem_u32(&Vs[0][0]);

    float S[2][8][4];
#pragma unroll
    for (int i = 0; i < 2; i++)
#pragma unroll
        for (int j = 0; j < 8; j++)
#pragma unroll
            for (int r = 0; r < 4; r++) S[i][j][r] = 0.f;

#pragma unroll
    for (int kc = 0; kc < 4; kc++) {
        uint32_t af[2][4], bf[8][2];
#pragma unroll
        for (int fm = 0; fm < 2; fm++) {
            const int m = wid * 32 + fm * 16 + aRow;
            LDSM_X4(af[fm][0], af[fm][1], af[fm][2], af[fm][3],
                    Qb + (uint32_t)(m * PQ + kc * 16 + aCol) * 2);
        }
#pragma unroll
        for (int g = 0; g < 4; g++) {
            const int nn = g * 16 + aRow;
            uint32_t r0, r1, r2, r3;
            LDSM_X4(r0, r1, r2, r3, Kb + (uint32_t)(nn * PQ + kc * 16 + aCol) * 2);
            bf[2 * g][0] = r0; bf[2 * g][1] = r2;
            bf[2 * g + 1][0] = r1; bf[2 * g + 1][1] = r3;
        }
#pragma unroll
        for (int fm = 0; fm < 2; fm++)
#pragma unroll
            for (int fn = 0; fn < 8; fn++)
                mma16(S[fm][fn], af[fm][0], af[fm][1], af[fm][2], af[fm][3],
                      bf[fn][0], bf[fn][1]);
    }

    constexpr float L2E = 1.4426950408889634f;
    float rsum[2][2] = {{0.f, 0.f}, {0.f, 0.f}};
#pragma unroll
    for (int fm = 0; fm < 2; fm++)
#pragma unroll
        for (int fn = 0; fn < 8; fn++) {
            float w0 = ex2f(S[fm][fn][0] * L2E);
            float w1 = ex2f(S[fm][fn][1] * L2E);
            float w2 = ex2f(S[fm][fn][2] * L2E);
            float w3 = ex2f(S[fm][fn][3] * L2E);
            S[fm][fn][0] = w0; S[fm][fn][1] = w1;
            S[fm][fn][2] = w2; S[fm][fn][3] = w3;
            rsum[fm][0] += w0 + w1;
            rsum[fm][1] += w2 + w3;
        }
#pragma unroll
    for (int fm = 0; fm < 2; fm++)
#pragma unroll
        for (int h = 0; h < 2; h++) {
            rsum[fm][h] += __shfl_xor_sync(0xffffffffu, rsum[fm][h], 1);
            rsum[fm][h] += __shfl_xor_sync(0xffffffffu, rsum[fm][h], 2);
        }

    uint32_t pf[2][4][4];
#pragma unroll
    for (int fm = 0; fm < 2; fm++)
#pragma unroll
        for (int kc = 0; kc < 4; kc++) {
            pf[fm][kc][0] = h2u(__floats2half2_rn(S[fm][2 * kc][0],     S[fm][2 * kc][1]));
            pf[fm][kc][1] = h2u(__floats2half2_rn(S[fm][2 * kc][2],     S[fm][2 * kc][3]));
            pf[fm][kc][2] = h2u(__floats2half2_rn(S[fm][2 * kc + 1][0], S[fm][2 * kc + 1][1]));
            pf[fm][kc][3] = h2u(__floats2half2_rn(S[fm][2 * kc + 1][2], S[fm][2 * kc + 1][3]));
        }

    float O[2][8][4];
#pragma unroll
    for (int i = 0; i < 2; i++)
#pragma unroll
        for (int j = 0; j < 8; j++)
#pragma unroll
            for (int r = 0; r < 4; r++) O[i][j][r] = 0.f;

#pragma unroll
    for (int kc = 0; kc < 4; kc++) {
        uint32_t bf[8][2];
#pragma unroll
        for (int g = 0; g < 4; g++) {
            LDSM_X4T(bf[2 * g][0], bf[2 * g][1], bf[2 * g + 1][0], bf[2 * g + 1][1],
                     Vb + (uint32_t)((kc * 16 + bRow) * PQ + g * 16 + bCol) * 2);
        }
#pragma unroll
        for (int fm = 0; fm < 2; fm++)
#pragma unroll
            for (int fn = 0; fn < 8; fn++)
                mma16(O[fm][fn], pf[fm][kc][0], pf[fm][kc][1], pf[fm][kc][2], pf[fm][kc][3],
                      bf[fn][0], bf[fn][1]);
    }

#pragma unroll
    for (int fm = 0; fm < 2; fm++) {
        const float inv0 = 1.f / rsum[fm][0];
        const float inv1 = 1.f / rsum[fm][1];
#pragma unroll
        for (int fn = 0; fn < 8; fn++) {
            const int d = fn * 8 + t4 * 2;
            const int r0 = qb + wid * 32 + fm * 16 + gid;
            __half* dst0 = g_attn + ((size_t)(b * NTOK + r0)) * CD + nh * HDIM + d;
            *(__half2*)dst0 = __floats2half2_rn(O[fm][fn][0] * inv0, O[fm][fn][1] * inv0);
            __half* dst1 = g_attn + ((size_t)(b * NTOK + r0 + 8)) * CD + nh * HDIM + d;
            *(__half2*)dst1 = __floats2half2_rn(O[fm][fn][2] * inv1, O[fm][fn][3] * inv1);
        }
    }
}

// ---------------- conversions ----------------
__global__ void round_h_k(const float* __restrict__ src, __half* __restrict__ dst, int n8)
{
    int i = blockIdx.x * 256 + threadIdx.x;
    if (i >= n8) return;
    float4 v0 = *(const float4*)(src + 8 * (size_t)i);
    float4 v1 = *(const float4*)(src + 8 * (size_t)i + 4);
    __half2* d = (__half2*)(dst + 8 * (size_t)i);
    d[0] = __floats2half2_rn(v0.x, v0.y);
    d[1] = __floats2half2_rn(v0.z, v0.w);
    d[2] = __floats2half2_rn(v1.x, v1.y);
    d[3] = __floats2half2_rn(v1.z, v1.w);
}

__global__ void round_w3_k(const float* __restrict__ Wq, const float* __restrict__ Wkv,
                           const float* __restrict__ Wp)
{
    int i = blockIdx.x * 256 + threadIdx.x;
    const float* src;
    __half* dst;
    int off;
    if (i < 32768)        { src = Wq;  dst = g_wqr;  off = i; }
    else if (i < 98304)   { src = Wkv; dst = g_wkvr; off = i - 32768; }
    else                  { src = Wp;  dst = g_wpr;  off = i - 98304; }
    float4 v0 = *(const float4*)(src + 8 * (size_t)off);
    float4 v1 = *(const float4*)(src + 8 * (size_t)off + 4);
    __half2* d = (__half2*)(dst + 8 * (size_t)off);
    d[0] = __floats2half2_rn(v0.x, v0.y);
    d[1] = __floats2half2_rn(v0.z, v0.w);
    d[2] = __floats2half2_rn(v1.x, v1.y);
    d[3] = __floats2half2_rn(v1.z, v1.w);
}

// ---------------- fused split-K reduce + layernorm -> fp16 ----------------
__global__ void reduce_ln_k(const float* __restrict__ gamma, const float* __restrict__ beta)
{
    int row = blockIdx.x;
    int t = threadIdx.x;
    const float* p = g_part + (size_t)row * CD;
    float a = 0.f, b2 = 0.f;
#pragma unroll
    for (int z = 0; z < SPLITK; z++) {
        a  += p[(size_t)z * (BB * MT * CD) + t];
        b2 += p[(size_t)z * (BB * MT * CD) + t + 256];
    }
    float s = a + b2, s2 = a * a + b2 * b2;
#pragma unroll
    for (int o = 16; o; o >>= 1) {
        s  += __shfl_down_sync(0xffffffffu, s,  o);
        s2 += __shfl_down_sync(0xffffffffu, s2, o);
    }
    __shared__ float rs[8], rs2[8];
    int w = t >> 5, l = t & 31;
    if (l == 0) { rs[w] = s; rs2[w] = s2; }
    __syncthreads();
    if (t == 0) {
        float S = 0.f, S2 = 0.f;
        for (int q2 = 0; q2 < 8; q2++) { S += rs[q2]; S2 += rs2[q2]; }
        float mu = S / (float)CD;
        float var = S2 / (float)CD - mu * mu;
        rs[0] = mu;
        rs2[0] = rsqrtf(var + 1e-3f);
    }
    __syncthreads();
    float mu = rs[0], inv = rs2[0];
    __half* out = g_lnh + (size_t)row * CD;
    out[t]       = __float2half((a  - mu) * inv * gamma[t]       + beta[t]);
    out[t + 256] = __float2half((b2 - mu) * inv * gamma[t + 256] + beta[t + 256]);
}

// ---------------- launch ----------------
extern "C" void kernel_launch(void* const* d_in, const int* in_sizes, int n_in,
                              void* d_out, int out_size)
{
    const float* x     = (const float*)d_in[0];
    const float* Wq    = (const float*)d_in[1];
    const float* Wkv   = (const float*)d_in[2];
    const float* convw = (const float*)d_in[3];
    const float* gamma = (const float*)d_in[4];
    const float* beta  = (const float*)d_in[5];
    const float* Wp    = (const float*)d_in[6];
    const float* bp    = (const float*)d_in[7];
    float* out = (float*)d_out;

    __half *xc, *cwr, *wqr, *wpr, *wkvr, *lnh, *attnp;
    float *part;
    cudaGetSymbolAddress((void**)&xc,    g_xc);
    cudaGetSymbolAddress((void**)&cwr,   g_cwr);
    cudaGetSymbolAddress((void**)&wqr,   g_wqr);
    cudaGetSymbolAddress((void**)&wpr,   g_wpr);
    cudaGetSymbolAddress((void**)&wkvr,  g_wkvr);
    cudaGetSymbolAddress((void**)&part,  g_part);
    cudaGetSymbolAddress((void**)&lnh,   g_lnh);
    cudaGetSymbolAddress((void**)&attnp, g_attn);

    static cudaStream_t sB = nullptr;
    static cudaEvent_t eFork = nullptr, eCW = nullptr;
    if (!sB) {
        cudaStreamCreateWithFlags(&sB, cudaStreamNonBlocking);
        cudaEventCreateWithFlags(&eFork, cudaEventDisableTiming);
        cudaEventCreateWithFlags(&eCW,   cudaEventDisableTiming);
        cudaFuncSetAttribute(mma_gemm<0, 0>, cudaFuncAttributeMaxDynamicSharedMemorySize, SMEM_BYTES);
        cudaFuncSetAttribute(mma_gemm<0, 3>, cudaFuncAttributeMaxDynamicSharedMemorySize, SMEM_BYTES);
        cudaFuncSetAttribute(fused_qconv_k, cudaFuncAttributeMaxDynamicSharedMemorySize, SMEM_BYTES);
        cudaFuncSetAttribute(attn_k, cudaFuncAttributeMaxDynamicSharedMemorySize, ATT_SMEM);
    }

    // fork: stream B converts conv_w (doesn't need x)
    cudaEventRecord(eFork, 0);
    cudaStreamWaitEvent(sB, eFork, 0);
    {
        int n8c = KIM * CD / 8;
        round_h_k<<<(n8c + 255) / 256, 256, 0, sB>>>(convw, cwr, n8c);
        cudaEventRecord(eCW, sB);
    }

    // main: x + small weights
    {
        int n8x = BB * NTOK * CD / 8;
        round_h_k<<<(n8x + 255) / 256, 256>>>(x, xc, n8x);
        round_w3_k<<<512, 256>>>(Wq, Wkv, Wp);
    }
    cudaStreamWaitEvent(0, eCW, 0);

    // merged conv-splitK + q GEMM (1280 CTAs)
    fused_qconv_k<<<1280, 128, SMEM_BYTES>>>(xc, cwr, wqr, part);

    // reduce+LN -> fp16, kv GEMM -> g_kvh
    reduce_ln_k<<<BB * MT, 256>>>(gamma, beta);
    mma_gemm<0, 3><<<dim3((2 * CD) / 128, (BB * MT) / 128), 128, SMEM_BYTES>>>(
        lnh, wkvr, nullptr, BB * MT, 2 * CD, CD, CD, nullptr);

    // tail: one attention launch, one Wp launch (no chunks, no events)
    attn_k<<<dim3(NTOK / 128, BB * NHEAD), 128, ATT_SMEM>>>();
    mma_gemm<0, 0><<<dim3(CD / 128, BB * NTOK / 128), 128, SMEM_BYTES>>>(
        attnp, wpr, out, BB * NTOK, CD, CD, CD, bp);
}